// round 3
// baseline (speedup 1.0000x reference)
#include <cuda_runtime.h>
#include <cstdint>
#include <math.h>

// Problem constants (fixed by dataset: B=65536, D=256, K=10)
#define KK 10
#define DD 256
#define BT 96                         // rows (threads) per block
#define L2PI_F 1.8378770664093453f    // fl32(log(2*pi))

typedef unsigned long long ull;

// ---- precomputed tables (device globals; no allocation allowed) ----
__device__ ull   g_nm [KK * 128];   // [k][p] = (-mu[k][2p], -mu[k][2p+1])
__device__ float g_ev [KK * DD];    // exp(lv)   (general path, unexercised when lv==0)
__device__ float g_lvt[KK * DD];    // lv        (general path)
__device__ int   g_fast;            // all logvar == 0 -> exact fast path
__device__ float g_logk;            // fl32(log(1/K))

// ---------- packed f32x2 helpers (per-lane .rn == scalar .rn bitwise) ----------
static __device__ __forceinline__ ull pack2(float x, float y) {
    ull r; asm("mov.b64 %0, {%1, %2};" : "=l"(r) : "f"(x), "f"(y)); return r;
}
static __device__ __forceinline__ void unpack2(ull v, float& x, float& y) {
    asm("mov.b64 {%0, %1}, %2;" : "=f"(x), "=f"(y) : "l"(v));
}
static __device__ __forceinline__ ull add2(ull a, ull b) {
    ull d; asm("add.rn.f32x2 %0, %1, %2;" : "=l"(d) : "l"(a), "l"(b)); return d;
}
static __device__ __forceinline__ ull mul2(ull a, ull b) {
    ull d; asm("mul.rn.f32x2 %0, %1, %2;" : "=l"(d) : "l"(a), "l"(b)); return d;
}

// ---------- kernel 0: build tables ----------
__global__ void k_prep(const float* __restrict__ mu, const float* __restrict__ lv) {
    __shared__ int nz;
    int t = threadIdx.x;
    if (t == 0) nz = 0;
    __syncthreads();

    int any = 0;
    for (int i = t; i < KK * 128; i += blockDim.x) {
        int k = i / 128, p = i % 128, d = 2 * p;
        float m0 = mu[k * DD + d], m1 = mu[k * DD + d + 1];
        float l0 = lv[k * DD + d], l1 = lv[k * DD + d + 1];
        g_nm[i] = pack2(-m0, -m1);
        g_ev [k * DD + d]     = expf(l0);
        g_ev [k * DD + d + 1] = expf(l1);
        g_lvt[k * DD + d]     = l0;
        g_lvt[k * DD + d + 1] = l1;
        if (l0 != 0.0f || l1 != 0.0f) any = 1;
    }
    if (any) atomicOr(&nz, 1);
    __syncthreads();
    if (t == 0) {
        g_fast = (nz == 0) ? 1 : 0;
        g_logk = (float)log((double)(1.0f / (float)KK));  // == fl32 of ln(0.1f)
    }
}

// ---------- kernel 1: logits, bitwise-emulating XLA:GPU row reduction ----------
// Per (b,k), over u_d = fl(fl((q_d-mu_d)^2) + L2PI), d = 0..255:
//   s_t = fl(u_{2t} + u_{2t+1}), t = 0..127          (vec2 per-thread pre-reduce)
//   per warp w (s indices 32w..32w+31): shfl_down tree offsets 16,8,4,2,1:
//     a_l = s_l + s_{l+16}; b_l = a_l + a_{l+8}; c_l = b_l + b_{l+4};
//     d_l = c_l + c_{l+2};  W_w = d_0 + d_1
//   cross-warp: L = fl(fl(W0+W2) + fl(W1+W3))        (init-0 padded shfl tree)
//   logit = fl(-0.5*L + logk)                        (-0.5 scale exact, commutes)
__global__ void __launch_bounds__(BT)
k_logits(const float* __restrict__ q, float* __restrict__ out, int nrows) {
    __shared__ ull   s_q[32][BT + 1];      // d-pairs of one 64-wide w-chunk, per row
    __shared__ ull   s_nm[KK * 128];       // -mu d-pair table
    __shared__ float s_W[2][KK][BT];       // cross-warp partial slots

    int t    = threadIdx.x;
    int row0 = blockIdx.x * BT;
    int row  = row0 + t;

    for (int i = t; i < KK * 128; i += BT) s_nm[i] = g_nm[i];

    const ull L2   = pack2(L2PI_F, L2PI_F);
    const int fast = g_fast;

    for (int w = 0; w < 4; w++) {
        __syncthreads();
        // stage q[row, 64w .. 64w+63] for BT rows; coalesced float4 loads
        #pragma unroll
        for (int s = 0; s < 16; s++) {
            int i  = t + BT * s;           // 0..1535
            int r  = i >> 4;               // row-in-block
            int f4 = i & 15;               // float4 index within 64 floats
            float4 v = make_float4(0.f, 0.f, 0.f, 0.f);
            int gr = row0 + r;
            if (gr < nrows)
                v = *reinterpret_cast<const float4*>(q + (size_t)gr * DD + w * 64 + 4 * f4);
            s_q[2 * f4 + 0][r] = pack2(v.x, v.y);
            s_q[2 * f4 + 1][r] = pack2(v.z, v.w);
        }
        __syncthreads();

        // hoist this row's chunk into registers (reused across all k)
        ull qq[32];
        #pragma unroll
        for (int l = 0; l < 32; l++) qq[l] = s_q[l][t];

        for (int k = 0; k < KK; k++) {
            float a[16];
            if (fast) {
                #pragma unroll
                for (int l = 0; l < 16; l++) {
                    ull nma = s_nm[k * 128 + w * 32 + l];
                    ull nmb = s_nm[k * 128 + w * 32 + 16 + l];
                    ull da  = add2(qq[l], nma);          // fl(q - mu), d-pair
                    ull ua  = add2(mul2(da, da), L2);    // fl(fl(diff^2) + L2PI)
                    ull db  = add2(qq[16 + l], nmb);
                    ull ub  = add2(mul2(db, db), L2);
                    float ax, ay, bx, by;
                    unpack2(ua, ax, ay);
                    unpack2(ub, bx, by);
                    // a_l = fl( s_l + s_{l+16} ),  s = fl(u_even + u_odd)
                    a[l] = __fadd_rn(__fadd_rn(ax, ay), __fadd_rn(bx, by));
                }
            } else {
                // general logvar path: u = fl(fl(fl(fl(d^2)/ev) + lv) + L2PI), same tree
                #pragma unroll
                for (int l = 0; l < 16; l++) {
                    float sa, sb;
                    {
                        float q0, q1, n0, n1;
                        unpack2(qq[l], q0, q1);
                        unpack2(s_nm[k * 128 + w * 32 + l], n0, n1);
                        int d0 = w * 64 + 2 * l;
                        float e0 = __ldg(&g_ev[k * DD + d0]),     e1 = __ldg(&g_ev[k * DD + d0 + 1]);
                        float v0 = __ldg(&g_lvt[k * DD + d0]),    v1 = __ldg(&g_lvt[k * DD + d0 + 1]);
                        float f0 = __fadd_rn(q0, n0), f1 = __fadd_rn(q1, n1);
                        float u0 = __fadd_rn(__fadd_rn(__fdiv_rn(__fmul_rn(f0, f0), e0), v0), L2PI_F);
                        float u1 = __fadd_rn(__fadd_rn(__fdiv_rn(__fmul_rn(f1, f1), e1), v1), L2PI_F);
                        sa = __fadd_rn(u0, u1);
                    }
                    {
                        float q0, q1, n0, n1;
                        unpack2(qq[16 + l], q0, q1);
                        unpack2(s_nm[k * 128 + w * 32 + 16 + l], n0, n1);
                        int d0 = w * 64 + 32 + 2 * l;
                        float e0 = __ldg(&g_ev[k * DD + d0]),     e1 = __ldg(&g_ev[k * DD + d0 + 1]);
                        float v0 = __ldg(&g_lvt[k * DD + d0]),    v1 = __ldg(&g_lvt[k * DD + d0 + 1]);
                        float f0 = __fadd_rn(q0, n0), f1 = __fadd_rn(q1, n1);
                        float u0 = __fadd_rn(__fadd_rn(__fdiv_rn(__fmul_rn(f0, f0), e0), v0), L2PI_F);
                        float u1 = __fadd_rn(__fadd_rn(__fdiv_rn(__fmul_rn(f1, f1), e1), v1), L2PI_F);
                        sb = __fadd_rn(u0, u1);
                    }
                    a[l] = __fadd_rn(sa, sb);
                }
            }

            // shfl_down tree levels 8,4,2,1 over a[0..15]
            float b4[8];
            #pragma unroll
            for (int l = 0; l < 8; l++) b4[l] = __fadd_rn(a[l], a[l + 8]);
            float c4[4];
            #pragma unroll
            for (int l = 0; l < 4; l++) c4[l] = __fadd_rn(b4[l], b4[l + 4]);
            float d2a = __fadd_rn(c4[0], c4[2]);
            float d2b = __fadd_rn(c4[1], c4[3]);
            float W   = __fadd_rn(d2a, d2b);

            int slot = w & 1;                 // W0,W2 -> slot0 ; W1,W3 -> slot1
            if (w < 2) s_W[slot][k][t] = W;
            else       s_W[slot][k][t] = __fadd_rn(s_W[slot][k][t], W);
        }
    }

    if (row < nrows) {
        float logk = g_logk;
        #pragma unroll
        for (int k = 0; k < KK; k++) {
            float L = __fadd_rn(s_W[0][k][t], s_W[1][k][t]);  // fl((W0+W2)+(W1+W3))
            out[(size_t)row * KK + k] = __fadd_rn(__fmul_rn(-0.5f, L), logk);
        }
    }
}

// ---------- kernel 2: softmax + argmax, XLA:GPU order for K=10 ----------
__global__ void k_finish(const float* __restrict__ logit,
                         float* __restrict__ qy,
                         float* __restrict__ ind,
                         int nrows) {
    int b = blockIdx.x * blockDim.x + threadIdx.x;
    if (b >= nrows) return;

    const float2* lp = reinterpret_cast<const float2*>(logit + (size_t)b * KK);
    float l[KK];
    #pragma unroll
    for (int i = 0; i < KK / 2; i++) { float2 v = lp[i]; l[2*i] = v.x; l[2*i+1] = v.y; }

    // max: exact in any order
    float m = l[0];
    #pragma unroll
    for (int k = 1; k < KK; k++) m = fmaxf(m, l[k]);

    // exp = libdevice expf (same bits as XLA:GPU __nv_expf)
    float e[KK];
    #pragma unroll
    for (int k = 0; k < KK; k++) e[k] = expf(__fadd_rn(l[k], -m));

    // shfl_down tree over one warp, lanes 10..31 = init(0):
    // ssum = [((e0+e8)+e4)+(e2+e6)] + [((e1+e9)+e5)+(e3+e7)]
    float s0 = __fadd_rn(__fadd_rn(__fadd_rn(e[0], e[8]), e[4]),
                         __fadd_rn(e[2], e[6]));
    float s1 = __fadd_rn(__fadd_rn(__fadd_rn(e[1], e[9]), e[5]),
                         __fadd_rn(e[3], e[7]));
    float ssum = __fadd_rn(s0, s1);

    float qv[KK];
    #pragma unroll
    for (int k = 0; k < KK; k++) qv[k] = __fdiv_rn(e[k], ssum);  // IEEE div.rn

    float2* qp = reinterpret_cast<float2*>(qy + (size_t)b * KK);
    #pragma unroll
    for (int i = 0; i < KK / 2; i++) qp[i] = make_float2(qv[2*i], qv[2*i+1]);

    // argmax over q_y, first occurrence on ties (jnp.argmax semantics)
    int best = 0; float bv = qv[0];
    #pragma unroll
    for (int k = 1; k < KK; k++)
        if (qv[k] > bv) { bv = qv[k]; best = k; }
    ind[b] = (float)best;
}

extern "C" void kernel_launch(void* const* d_in, const int* in_sizes, int n_in,
                              void* d_out, int out_size) {
    const float* q_z = (const float*)d_in[0];   // [B, 256]
    const float* mu  = (const float*)d_in[1];   // [10, 256]
    const float* lv  = (const float*)d_in[2];   // [10, 256]

    int nrows = in_sizes[0] / DD;

    float* out_logit = (float*)d_out;                    // [B, 10]
    float* out_qy    = out_logit + (size_t)nrows * KK;   // [B, 10]
    float* out_ind   = out_qy    + (size_t)nrows * KK;   // [B]

    k_prep<<<1, 256>>>(mu, lv);
    k_logits<<<(nrows + BT - 1) / BT, BT>>>(q_z, out_logit, nrows);
    k_finish<<<(nrows + 255) / 256, 256>>>(out_logit, out_qy, out_ind, nrows);
}